// round 14
// baseline (speedup 1.0000x reference)
#include <cuda_runtime.h>
#include <cuda.h>
#include <cuda_fp16.h>
#include <math.h>
#include <cstdint>

#define BSZ 4
#define TT 2048
#define CC 2048
#define NH 16
#define HD 128
#define MM (BSZ*TT)   // 8192

// ---------------- scratch (device globals: no allocation allowed) -------------
__device__ float g_cos[TT*(HD/2)];
__device__ float g_sin[TT*(HD/2)];
__device__ __align__(1024) __half g_xh[(size_t)MM*CC];
__device__ __align__(1024) __half g_yh[(size_t)MM*CC];
__device__ __align__(1024) __half g_wh[4][(size_t)CC*CC];
__device__ __align__(1024) __half g_qh[(size_t)BSZ*NH*TT*HD];
__device__ __align__(1024) __half g_kh[(size_t)BSZ*NH*TT*HD];
__device__ __align__(1024) __half g_vh[(size_t)BSZ*NH*TT*HD];

// ---------------- PTX helpers --------------------------------------------------
__device__ __forceinline__ uint32_t smem_u32(const void* p) {
    uint32_t a;
    asm("{ .reg .u64 t; cvta.to.shared.u64 t, %1; cvt.u32.u64 %0, t; }" : "=r"(a) : "l"(p));
    return a;
}
#define MBAR_INIT(a, n) asm volatile("mbarrier.init.shared.b64 [%0], %1;" :: "r"(a), "r"(n) : "memory")
#define MBAR_ARRIVE(a)  asm volatile("mbarrier.arrive.shared.b64 _, [%0];" :: "r"(a) : "memory")
#define MBAR_EXPECT(a, tx) asm volatile("mbarrier.arrive.expect_tx.shared.b64 _, [%0], %1;" :: "r"(a), "r"(tx) : "memory")
#define MBAR_WAIT(a, ph) do {                                                      \
    uint32_t _m = (a), _p = (ph), _d;                                              \
    asm volatile("{\n\t.reg .pred p;\n\t"                                          \
        "mbarrier.try_wait.parity.acquire.cta.shared::cta.b64 p, [%1], %2;\n\t"    \
        "selp.b32 %0, 1, 0, p;\n\t}" : "=r"(_d) : "r"(_m), "r"(_p) : "memory");    \
    if (!_d) {                                                                     \
        asm volatile("{\n\t.reg .pred P1;\n\t"                                     \
            "WL_%=:\n\t"                                                           \
            "mbarrier.try_wait.parity.acquire.cta.shared::cta.b64 P1, [%0], %1, 0x989680;\n\t" \
            "@P1 bra.uni WD_%=;\n\tbra.uni WL_%=;\n\tWD_%=:\n\t}"                  \
            :: "r"(_m), "r"(_p) : "memory");                                       \
    }                                                                              \
} while (0)
#define TMA2D(dst, map, cx, cy, mb) \
    asm volatile("cp.async.bulk.tensor.2d.shared::cta.global.tile.mbarrier::complete_tx::bytes " \
        "[%0], [%1, {%2, %3}], [%4];" \
        :: "r"(dst), "l"(map), "r"(cx), "r"(cy), "r"(mb) : "memory")

__device__ __forceinline__ void ldmx4(uint32_t* r, uint32_t addr) {
    asm volatile("ldmatrix.sync.aligned.m8n8.x4.shared.b16 {%0,%1,%2,%3}, [%4];"
                 : "=r"(r[0]), "=r"(r[1]), "=r"(r[2]), "=r"(r[3]) : "r"(addr));
}
__device__ __forceinline__ void ldmx4t(uint32_t* r, uint32_t addr) {
    asm volatile("ldmatrix.sync.aligned.m8n8.x4.trans.shared.b16 {%0,%1,%2,%3}, [%4];"
                 : "=r"(r[0]), "=r"(r[1]), "=r"(r[2]), "=r"(r[3]) : "r"(addr));
}
__device__ __forceinline__ void mmaf16(float* d, const uint32_t* a,
                                       uint32_t b0, uint32_t b1) {
    asm volatile("mma.sync.aligned.m16n8k16.row.col.f32.f16.f16.f32 "
                 "{%0,%1,%2,%3}, {%4,%5,%6,%7}, {%8,%9}, {%0,%1,%2,%3};"
                 : "+f"(d[0]), "+f"(d[1]), "+f"(d[2]), "+f"(d[3])
                 : "r"(a[0]), "r"(a[1]), "r"(a[2]), "r"(a[3]), "r"(b0), "r"(b1));
}
__device__ __forceinline__ uint32_t packf16(float lo, float hi) {
    uint32_t r;
    asm("cvt.rn.f16x2.f32 %0, %1, %2;" : "=r"(r) : "f"(hi), "f"(lo));
    return r;
}
__device__ __forceinline__ float f16val(float x) {
    return __half2float(__float2half(x));
}
__device__ __forceinline__ uint32_t swzoff(int r, int chunk) {
    return (uint32_t)(r * 128 + ((chunk ^ (r & 7)) << 4));
}

// ---------------- RoPE cos/sin table -------------------------------------------
__global__ void rope_table_kernel() {
    int idx = blockIdx.x * blockDim.x + threadIdx.x;
    if (idx >= TT * (HD/2)) return;
    int t = idx / (HD/2);
    int i = idx % (HD/2);
    float inv = (float)pow(10000.0, -(double)(2*i) / (double)HD);
    float ang = (float)t * inv;
    g_cos[idx] = cosf(ang);
    g_sin[idx] = sinf(ang);
}

// ---------------- fp32 -> f16 (hi only), MLP=4 grid-stride -----------------------
__global__ void cvt_hi_kernel(const float* __restrict__ in,
                              __half* __restrict__ hi, int n4) {
    int tid = blockIdx.x * blockDim.x + threadIdx.x;
    int stride = gridDim.x * blockDim.x;
    float4 v[4];
    int idx[4];
#pragma unroll
    for (int k = 0; k < 4; k++) {
        idx[k] = tid + k * stride;
        if (idx[k] < n4) v[k] = ((const float4*)in)[idx[k]];
    }
#pragma unroll
    for (int k = 0; k < 4; k++) {
        if (idx[k] < n4) {
            uint2 o;
            o.x = packf16(v[k].x, v[k].y);
            o.y = packf16(v[k].z, v[k].w);
            ((uint2*)hi)[idx[k]] = o;
        }
    }
}

// ---------------- fp32 -> f16 hi, 4 weights, MLP=4 -------------------------------
__global__ void cvt_w4_kernel(const float* __restrict__ w0, const float* __restrict__ w1,
                              const float* __restrict__ w2, const float* __restrict__ w3,
                              __half* __restrict__ hi, int n4) {
    int tid = blockIdx.x * blockDim.x + threadIdx.x;
    int stride = gridDim.x * blockDim.x;
    int z = blockIdx.y;
    const float* in = (z == 0) ? w0 : (z == 1) ? w1 : (z == 2) ? w2 : w3;
    size_t base = (size_t)z * CC * CC / 4;
    float4 v[4];
    int idx[4];
#pragma unroll
    for (int k = 0; k < 4; k++) {
        idx[k] = tid + k * stride;
        if (idx[k] < n4) v[k] = ((const float4*)in)[idx[k]];
    }
#pragma unroll
    for (int k = 0; k < 4; k++) {
        if (idx[k] < n4) {
            uint2 h;
            h.x = packf16(v[k].x, v[k].y);
            h.y = packf16(v[k].z, v[k].w);
            ((uint2*)hi)[base + idx[k]] = h;
        }
    }
}

// ---------------- persistent f16 single-pass GEMM via TMA + mma.sync -------------
// CTA tile 256(M) x 128(N), BK=128 (2x 64-col SW128 subtiles), 2-stage flat
// cross-tile TMA pipeline, 512 threads / 16 warps (4m x 4n), warp tile 64x32.
// Fragment double-buffering: LDSM for ks+1 issued before mma of ks.
// MODE 0: out-proj (fp32 out). MODE 1: qkv (f16-hi out, RoPE for z<2).
#define BM 256
#define BN 128
#define BK 128
#define NKIT (CC / BK)     // 16
#define B_OFF 65536        // A subtiles @0,32768; B subtiles @65536,81920
#define STG_SZ 98304
#define NSTG 2
#define GEMM_SMEM (2048 + NSTG*STG_SZ)
#define GTHREADS 512
#define GWARPS (GTHREADS/32)

template<int MODE>
__global__ __launch_bounds__(GTHREADS, 1)
void gemm_pers(const __grid_constant__ CUtensorMap tmA,
               const __grid_constant__ CUtensorMap tmB0,
               const __grid_constant__ CUtensorMap tmB1,
               const __grid_constant__ CUtensorMap tmB2,
               __half* __restrict__ qh,
               __half* __restrict__ kh,
               __half* __restrict__ vh,
               float* __restrict__ out) {
    extern __shared__ char smraw[];
    const uint32_t raw = smem_u32(smraw);
    const uint32_t ab = (raw + 64 + 1023) & ~1023u;
    const uint32_t fullb = raw;          // NSTG x 8B
    const uint32_t emptyb = raw + 16;    // NSTG x 8B
    const int tid = threadIdx.x;
    const int wid = tid >> 5, lane = tid & 31;
    const int wm = wid >> 2;             // 0..3  (64 rows each)
    const int wn = wid & 3;              // 0..3  (32 cols each)
    const int NT = (MODE == 1) ? (3 * (MM/BM) * (CC/BN)) : ((MM/BM) * (CC/BN));
    const int bx = blockIdx.x;
    const int grid = gridDim.x;
    if (bx >= NT) return;
    const int myTiles = (NT - bx + grid - 1) / grid;
    const int myChunks = myTiles * NKIT;

    if (tid == 0) {
#pragma unroll
        for (int s = 0; s < NSTG; s++) {
            MBAR_INIT(fullb + s * 8, 1);
            MBAR_INIT(emptyb + s * 8, GWARPS);   // warp-granular arrivals
        }
        asm volatile("fence.proxy.async.shared::cta;" ::: "memory");
    }
    __syncthreads();

    auto issue = [&](int g) {
        int lt = g >> 4;          // local tile (16 chunks/tile)
        int c = g & 15;
        int t = bx + lt * grid;
        int s = g & 1;
        uint32_t sb = ab + s * STG_SZ;
        uint32_t mb = fullb + s * 8;
        int z, mbk, nb;
        if (MODE == 1) { z = t >> 9; int r = t & 511; mbk = r >> 4; nb = r & 15; }
        else { z = 0; mbk = t >> 4; nb = t & 15; }
        const CUtensorMap* pb = (z == 0) ? &tmB0 : (z == 1) ? &tmB1 : &tmB2;
        MBAR_EXPECT(mb, (uint32_t)STG_SZ);
        int cx = c * BK;
        TMA2D(sb,             &tmA, cx,      mbk * BM, mb);
        TMA2D(sb + 32768,     &tmA, cx + 64, mbk * BM, mb);
        TMA2D(sb + B_OFF,     pb,   cx,      nb * BN, mb);
        TMA2D(sb + B_OFF + 16384, pb, cx + 64, nb * BN, mb);
    };

    if (tid == 0) {
        for (int g = 0; g < NSTG && g < myChunks; g++) issue(g);
    }

    float acc[4][4][4];
#pragma unroll
    for (int i = 0; i < 4; i++)
#pragma unroll
        for (int j = 0; j < 4; j++)
#pragma unroll
            for (int q = 0; q < 4; q++) acc[i][j][q] = 0.f;

    const int a_row = wm * 64 + (lane & 15);
    const int a_csel = lane >> 4;
    const int b_row = wn * 32 + ((lane >> 4) << 3) + (lane & 7);
    const int b_csel = (lane >> 3) & 1;
    const int tr = lane >> 2;
    const int tc = (lane & 3) << 1;

    for (int g = 0; g < myChunks; ++g) {
        int s = g & 1;
        int ph = (g >> 1) & 1;
        MBAR_WAIT(fullb + s * 8, ph);

        uint32_t sb = ab + s * STG_SZ;
        uint32_t a4[2][4][4], b4[2][2][4];

        // load fragments for a ks step into buffer buf
        auto loadf = [&](int ks, int buf) {
            int hf = ks >> 2;
            int lc = (ks & 3) << 1;
            uint32_t abase = sb + hf * 32768;
            uint32_t bbase = sb + B_OFF + hf * 16384;
#pragma unroll
            for (int f = 0; f < 4; f++)
                ldmx4(a4[buf][f], abase + swzoff(a_row + f * 16, lc + a_csel));
#pragma unroll
            for (int p = 0; p < 2; p++)
                ldmx4(b4[buf][p], bbase + swzoff(b_row + p * 16, lc + b_csel));
        };

        loadf(0, 0);
#pragma unroll
        for (int ks = 0; ks < 8; ks++) {
            int cur = ks & 1;
            if (ks < 7) loadf(ks + 1, cur ^ 1);   // prefetch next step's fragments
#pragma unroll
            for (int mf = 0; mf < 4; mf++)
#pragma unroll
                for (int nf = 0; nf < 4; nf++) {
                    int p = nf >> 1;
                    int e = (nf & 1) << 1;
                    mmaf16(acc[mf][nf], a4[cur][mf], b4[cur][p][e], b4[cur][p][e + 1]);
                }
        }
        if (lane == 0) MBAR_ARRIVE(emptyb + s * 8);   // one arrive per warp

        if (tid == 0 && g + NSTG < myChunks) {
            MBAR_WAIT(emptyb + s * 8, ph);
            issue(g + NSTG);
        }

        if ((g & 15) == 15) {
            // ---- epilogue for tile (g>>4); next tile's TMA already in flight ----
            int t = bx + (g >> 4) * grid;
            int z, mbk, nb;
            if (MODE == 1) { z = t >> 9; int r = t & 511; mbk = r >> 4; nb = r & 15; }
            else { z = 0; mbk = t >> 4; nb = t & 15; }
            int m0 = mbk * BM, n0 = nb * BN;
            __half* outH = (z == 0) ? qh : (z == 1) ? kh : vh;
            bool rope = (z < 2);
#pragma unroll
            for (int mf = 0; mf < 4; mf++) {
#pragma unroll
                for (int nf = 0; nf < 4; nf++) {
                    int mA = m0 + wm * 64 + mf * 16 + tr;
                    int n  = n0 + wn * 32 + nf * 8 + tc;
                    float* d = acc[mf][nf];
#pragma unroll
                    for (int hf = 0; hf < 2; hf++) {
                        int m = mA + hf * 8;
                        float e = d[hf * 2], o = d[hf * 2 + 1];
                        if (MODE == 0) {
                            float2 v2 = {e, o};
                            *(float2*)(out + (size_t)m * CC + n) = v2;
                        } else {
                            int b = m >> 11;
                            int tt = m & (TT - 1);
                            int h = n >> 7;
                            int dd = n & (HD - 1);
                            size_t dst = ((size_t)(b * NH + h) * TT + tt) * HD + dd;
                            float e2 = e, o2 = o;
                            if (rope) {
                                float cv = g_cos[tt * (HD/2) + (dd >> 1)];
                                float sv = g_sin[tt * (HD/2) + (dd >> 1)];
                                e2 = e * cv - o * sv;
                                o2 = o * cv + e * sv;
                            }
                            *(uint32_t*)((char*)outH + dst * 2) = packf16(e2, o2);
                        }
                        d[hf * 2] = 0.f; d[hf * 2 + 1] = 0.f;
                    }
                }
            }
        }
    }
}

// ---------------- tensor-core flash attention (f16 hi, causal) -------------------
// QK = Qh*Kh, PV = Ph*Vh. smem: Qh 16K | Kh 16K | Vh 16K.
#define SQH 0
#define SKH 16384
#define SVH 32768
#define ATTN_SMEM (1024 + 49152)

__global__ __launch_bounds__(128, 2)
void attn_tc(const __grid_constant__ CUtensorMap mQh,
             const __grid_constant__ CUtensorMap mKh,
             const __grid_constant__ CUtensorMap mVh,
             __half* __restrict__ yh) {
    extern __shared__ char smraw[];
    const uint32_t raw = smem_u32(smraw);
    const uint32_t ab = (raw + 64 + 1023) & ~1023u;
    const uint32_t qfull = raw, kfull = raw + 8, vfull = raw + 16;
    const uint32_t kempty = raw + 24, vempty = raw + 32;
    const int tid = threadIdx.x, wid = tid >> 5, lane = tid & 31;
    const int qtile = gridDim.x - 1 - blockIdx.x;   // big tiles first
    const int bh = blockIdx.y;
    const int nt = qtile + 1;
    const int grow_q = bh * TT + qtile * 64;
    const int grow_k = bh * TT;

    if (tid == 0) {
        MBAR_INIT(qfull, 1); MBAR_INIT(kfull, 1); MBAR_INIT(vfull, 1);
        MBAR_INIT(kempty, 4); MBAR_INIT(vempty, 4);
        asm volatile("fence.proxy.async.shared::cta;" ::: "memory");
    }
    __syncthreads();
    if (tid == 0) {
        MBAR_EXPECT(qfull, 16384u);
        TMA2D(ab + SQH,        &mQh, 0,  grow_q, qfull);
        TMA2D(ab + SQH + 8192, &mQh, 64, grow_q, qfull);
        MBAR_EXPECT(kfull, 16384u);
        TMA2D(ab + SKH,        &mKh, 0,  grow_k, kfull);
        TMA2D(ab + SKH + 8192, &mKh, 64, grow_k, kfull);
        MBAR_EXPECT(vfull, 16384u);
        TMA2D(ab + SVH,        &mVh, 0,  grow_k, vfull);
        TMA2D(ab + SVH + 8192, &mVh, 64, grow_k, vfull);
    }

    float o[16][4];
#pragma unroll
    for (int i = 0; i < 16; i++)
#pragma unroll
        for (int q = 0; q < 4; q++) o[i][q] = 0.f;
    float m0r = -1e30f, m1r = -1e30f, l0r = 0.f, l1r = 0.f;

    const int q_row = wid * 16 + (lane & 15);
    const int q_csel = lane >> 4;
    const int k_rowbase = ((lane >> 4) << 3) + (lane & 7);
    const int k_csel = (lane >> 3) & 1;
    const int v_rowin = (lane & 7) + (((lane >> 3) & 1) << 3);
    const int v_csel = lane >> 4;
    const float scale = 0.08838834764831843f;

    MBAR_WAIT(qfull, 0);

    for (int j = 0; j < nt; j++) {
        MBAR_WAIT(kfull, j & 1);

        float s[8][4];
#pragma unroll
        for (int nf = 0; nf < 8; nf++)
#pragma unroll
            for (int q = 0; q < 4; q++) s[nf][q] = 0.f;

#pragma unroll
        for (int ks = 0; ks < 8; ks++) {
            int hf = ks >> 2;
            int lc = (ks & 3) << 1;
            uint32_t qh4[4];
            uint32_t qoff = hf * 8192 + swzoff(q_row, lc + q_csel);
            ldmx4(qh4, ab + SQH + qoff);
#pragma unroll
            for (int p = 0; p < 4; p++) {
                uint32_t kh4[4];
                uint32_t koff = hf * 8192 + swzoff(p * 16 + k_rowbase, lc + k_csel);
                ldmx4(kh4, ab + SKH + koff);
#pragma unroll
                for (int e2 = 0; e2 < 2; e2++) {
                    int nf = p * 2 + e2;
                    int e = e2 << 1;
                    mmaf16(s[nf], qh4, kh4[e], kh4[e + 1]);
                }
            }
        }
        if (lane == 0) MBAR_ARRIVE(kempty);
        if (tid == 0 && j + 1 < nt) {
            MBAR_WAIT(kempty, j & 1);
            MBAR_EXPECT(kfull, 16384u);
            int cy = grow_k + (j + 1) * 64;
            TMA2D(ab + SKH,        &mKh, 0,  cy, kfull);
            TMA2D(ab + SKH + 8192, &mKh, 64, cy, kfull);
        }

#pragma unroll
        for (int nf = 0; nf < 8; nf++)
#pragma unroll
            for (int q = 0; q < 4; q++) s[nf][q] *= scale;
        if (j == qtile) {
            int r0 = wid * 16 + (lane >> 2);
#pragma unroll
            for (int nf = 0; nf < 8; nf++) {
                int c0 = nf * 8 + ((lane & 3) << 1);
                if (c0     > r0)     s[nf][0] = -1e30f;
                if (c0 + 1 > r0)     s[nf][1] = -1e30f;
                if (c0     > r0 + 8) s[nf][2] = -1e30f;
                if (c0 + 1 > r0 + 8) s[nf][3] = -1e30f;
            }
        }

        float rm0 = -1e30f, rm1 = -1e30f;
#pragma unroll
        for (int nf = 0; nf < 8; nf++) {
            rm0 = fmaxf(rm0, fmaxf(s[nf][0], s[nf][1]));
            rm1 = fmaxf(rm1, fmaxf(s[nf][2], s[nf][3]));
        }
        rm0 = fmaxf(rm0, __shfl_xor_sync(0xffffffffu, rm0, 1));
        rm0 = fmaxf(rm0, __shfl_xor_sync(0xffffffffu, rm0, 2));
        rm1 = fmaxf(rm1, __shfl_xor_sync(0xffffffffu, rm1, 1));
        rm1 = fmaxf(rm1, __shfl_xor_sync(0xffffffffu, rm1, 2));
        float mn0 = fmaxf(m0r, rm0), mn1 = fmaxf(m1r, rm1);
        float al0 = __expf(m0r - mn0), al1 = __expf(m1r - mn1);
        m0r = mn0; m1r = mn1;

        float rs0 = 0.f, rs1 = 0.f;
        uint32_t aph[4][4];
#pragma unroll
        for (int ks2 = 0; ks2 < 4; ks2++) {
#pragma unroll
            for (int hn = 0; hn < 2; hn++) {
                int nf = 2 * ks2 + hn;
                float p0 = __expf(s[nf][0] - mn0);
                float p1 = __expf(s[nf][1] - mn0);
                float p2 = __expf(s[nf][2] - mn1);
                float p3 = __expf(s[nf][3] - mn1);
                rs0 += p0 + p1; rs1 += p2 + p3;
                aph[ks2][hn * 2]     = packf16(p0, p1);
                aph[ks2][hn * 2 + 1] = packf16(p2, p3);
            }
        }
        rs0 += __shfl_xor_sync(0xffffffffu, rs0, 1);
        rs0 += __shfl_xor_sync(0xffffffffu, rs0, 2);
        rs1 += __shfl_xor_sync(0xffffffffu, rs1, 1);
        rs1 += __shfl_xor_sync(0xffffffffu, rs1, 2);
        l0r = l0r * al0 + rs0;
        l1r = l1r * al1 + rs1;

#pragma unroll
        for (int ng = 0; ng < 16; ng++) {
            o[ng][0] *= al0; o[ng][1] *= al0;
            o[ng][2] *= al1; o[ng][3] *= al1;
        }

        MBAR_WAIT(vfull, j & 1);
#pragma unroll
        for (int ks2 = 0; ks2 < 4; ks2++) {
#pragma unroll
            for (int g = 0; g < 8; g++) {
                uint32_t vh4[4];
                int hf = g >> 2;
                uint32_t voff = hf * 8192 +
                                swzoff(ks2 * 16 + v_rowin, ((g & 3) << 1) + v_csel);
                ldmx4t(vh4, ab + SVH + voff);
#pragma unroll
                for (int e2 = 0; e2 < 2; e2++) {
                    int ng = g * 2 + e2;
                    int e = e2 << 1;
                    mmaf16(o[ng], aph[ks2], vh4[e], vh4[e + 1]);
                }
            }
        }
        if (lane == 0) MBAR_ARRIVE(vempty);
        if (tid == 0 && j + 1 < nt) {
            MBAR_WAIT(vempty, j & 1);
            MBAR_EXPECT(vfull, 16384u);
            int cy = grow_k + (j + 1) * 64;
            TMA2D(ab + SVH,        &mVh, 0,  cy, vfull);
            TMA2D(ab + SVH + 8192, &mVh, 64, cy, vfull);
        }
    }

    // epilogue: y (B,T,C) f16 hi
    float inv0 = 1.0f / l0r, inv1 = 1.0f / l1r;
    int b = bh >> 4, h = bh & 15;
    int t0 = qtile * 64 + wid * 16 + (lane >> 2);
    size_t base0 = (size_t)(b * TT + t0) * CC + h * HD;
    size_t base1 = base0 + (size_t)8 * CC;
    int c0 = (lane & 3) << 1;
#pragma unroll
    for (int ng = 0; ng < 16; ng++) {
        int col = ng * 8 + c0;
        *(uint32_t*)((char*)yh + (base0 + col) * 2) =
            packf16(o[ng][0] * inv0, o[ng][1] * inv0);
        *(uint32_t*)((char*)yh + (base1 + col) * 2) =
            packf16(o[ng][2] * inv1, o[ng][3] * inv1);
    }
}

// ---------------- host: tensormap encode via driver entry point ------------------
typedef CUresult (*EncodeFn)(CUtensorMap*, CUtensorMapDataType, cuuint32_t, void*,
                             const cuuint64_t*, const cuuint64_t*, const cuuint32_t*,
                             const cuuint32_t*, CUtensorMapInterleave, CUtensorMapSwizzle,
                             CUtensorMapL2promotion, CUtensorMapFloatOOBfill);

static void mk_map(EncodeFn enc, CUtensorMap* m, void* base, uint64_t cols,
                   uint64_t rows, uint32_t boxRows) {
    cuuint64_t dims[2] = {(cuuint64_t)cols, (cuuint64_t)rows};
    cuuint64_t strides[1] = {(cuuint64_t)cols * 2};
    cuuint32_t box[2] = {64u, boxRows};
    cuuint32_t es[2] = {1u, 1u};
    enc(m, CU_TENSOR_MAP_DATA_TYPE_FLOAT16, 2, base, dims, strides, box, es,
        CU_TENSOR_MAP_INTERLEAVE_NONE, CU_TENSOR_MAP_SWIZZLE_128B,
        CU_TENSOR_MAP_L2_PROMOTION_L2_128B, CU_TENSOR_MAP_FLOAT_OOB_FILL_NONE);
}

// ---------------- launch --------------------------------------------------------
extern "C" void kernel_launch(void* const* d_in, const int* in_sizes, int n_in,
                              void* d_out, int out_size) {
    const float* x  = (const float*)d_in[0];
    const float* Wq = (const float*)d_in[1];
    const float* Wk = (const float*)d_in[2];
    const float* Wv = (const float*)d_in[3];
    const float* Wp = (const float*)d_in[4];
    float* out = (float*)d_out;

    __half *xh, *yh, *wh;
    __half *qh, *kh, *vh;
    cudaGetSymbolAddress((void**)&xh, g_xh);
    cudaGetSymbolAddress((void**)&yh, g_yh);
    cudaGetSymbolAddress((void**)&wh, g_wh);
    cudaGetSymbolAddress((void**)&qh, g_qh);
    cudaGetSymbolAddress((void**)&kh, g_kh);
    cudaGetSymbolAddress((void**)&vh, g_vh);

    void* fn = nullptr;
    cudaDriverEntryPointQueryResult st;
    cudaGetDriverEntryPoint("cuTensorMapEncodeTiled", &fn, cudaEnableDefault, &st);
    EncodeFn enc = (EncodeFn)fn;
    const uint64_t QR = (uint64_t)BSZ * NH * TT;
    CUtensorMap mXh, mYh, mWh[4];
    CUtensorMap mQh, mKh, mVh;
    mk_map(enc, &mXh, xh, CC, MM, BM);
    mk_map(enc, &mYh, yh, CC, MM, BM);
    for (int i = 0; i < 4; i++)
        mk_map(enc, &mWh[i], wh + (size_t)i * CC * CC, CC, CC, BN);
    mk_map(enc, &mQh, qh, HD, QR, 64);
    mk_map(enc, &mKh, kh, HD, QR, 64);
    mk_map(enc, &mVh, vh, HD, QR, 64);

    int sms = 148;
    cudaDeviceGetAttribute(&sms, cudaDevAttrMultiProcessorCount, 0);

    rope_table_kernel<<<(TT * (HD/2) + 255) / 256, 256>>>();

    const int NX4 = MM * CC / 4;
    const int NW4 = CC * CC / 4;
    cvt_hi_kernel<<<(NX4/4 + 255) / 256, 256>>>(x, xh, NX4);
    cvt_w4_kernel<<<dim3((NW4/4 + 255) / 256, 4), 256>>>(Wq, Wk, Wv, Wp, wh, NW4);

    cudaFuncSetAttribute(gemm_pers<0>, cudaFuncAttributeMaxDynamicSharedMemorySize, GEMM_SMEM);
    cudaFuncSetAttribute(gemm_pers<1>, cudaFuncAttributeMaxDynamicSharedMemorySize, GEMM_SMEM);
    cudaFuncSetAttribute(attn_tc, cudaFuncAttributeMaxDynamicSharedMemorySize, ATTN_SMEM);

    gemm_pers<1><<<sms, GTHREADS, GEMM_SMEM>>>(mXh, mWh[0], mWh[1], mWh[2],
                                               qh, kh, vh, out);

    attn_tc<<<dim3(TT / 64, BSZ * NH), 128, ATTN_SMEM>>>(mQh, mKh, mVh, yh);

    gemm_pers<0><<<sms, GTHREADS, GEMM_SMEM>>>(mYh, mWh[3], mWh[3], mWh[3],
                                               qh, kh, vh, out);
}

// round 15
// speedup vs baseline: 1.0595x; 1.0595x over previous
#include <cuda_runtime.h>
#include <cuda.h>
#include <cuda_fp16.h>
#include <math.h>
#include <cstdint>

#define BSZ 4
#define TT 2048
#define CC 2048
#define NH 16
#define HD 128
#define MM (BSZ*TT)   // 8192

// ---------------- scratch (device globals: no allocation allowed) -------------
__device__ float g_cos[TT*(HD/2)];
__device__ float g_sin[TT*(HD/2)];
__device__ __align__(1024) __half g_xh[(size_t)MM*CC];
__device__ __align__(1024) __half g_yh[(size_t)MM*CC];
__device__ __align__(1024) __half g_wh[4][(size_t)CC*CC];
__device__ __align__(1024) __half g_qh[(size_t)BSZ*NH*TT*HD];
__device__ __align__(1024) __half g_kh[(size_t)BSZ*NH*TT*HD];
__device__ __align__(1024) __half g_vh[(size_t)BSZ*NH*TT*HD];

// ---------------- PTX helpers --------------------------------------------------
__device__ __forceinline__ uint32_t smem_u32(const void* p) {
    uint32_t a;
    asm("{ .reg .u64 t; cvta.to.shared.u64 t, %1; cvt.u32.u64 %0, t; }" : "=r"(a) : "l"(p));
    return a;
}
#define MBAR_INIT(a, n) asm volatile("mbarrier.init.shared.b64 [%0], %1;" :: "r"(a), "r"(n) : "memory")
#define MBAR_ARRIVE(a)  asm volatile("mbarrier.arrive.shared.b64 _, [%0];" :: "r"(a) : "memory")
#define MBAR_EXPECT(a, tx) asm volatile("mbarrier.arrive.expect_tx.shared.b64 _, [%0], %1;" :: "r"(a), "r"(tx) : "memory")
#define MBAR_WAIT(a, ph) do {                                                      \
    uint32_t _m = (a), _p = (ph), _d;                                              \
    asm volatile("{\n\t.reg .pred p;\n\t"                                          \
        "mbarrier.try_wait.parity.acquire.cta.shared::cta.b64 p, [%1], %2;\n\t"    \
        "selp.b32 %0, 1, 0, p;\n\t}" : "=r"(_d) : "r"(_m), "r"(_p) : "memory");    \
    if (!_d) {                                                                     \
        asm volatile("{\n\t.reg .pred P1;\n\t"                                     \
            "WL_%=:\n\t"                                                           \
            "mbarrier.try_wait.parity.acquire.cta.shared::cta.b64 P1, [%0], %1, 0x989680;\n\t" \
            "@P1 bra.uni WD_%=;\n\tbra.uni WL_%=;\n\tWD_%=:\n\t}"                  \
            :: "r"(_m), "r"(_p) : "memory");                                       \
    }                                                                              \
} while (0)
#define TMA2D(dst, map, cx, cy, mb) \
    asm volatile("cp.async.bulk.tensor.2d.shared::cta.global.tile.mbarrier::complete_tx::bytes " \
        "[%0], [%1, {%2, %3}], [%4];" \
        :: "r"(dst), "l"(map), "r"(cx), "r"(cy), "r"(mb) : "memory")

__device__ __forceinline__ void ldmx4(uint32_t* r, uint32_t addr) {
    asm volatile("ldmatrix.sync.aligned.m8n8.x4.shared.b16 {%0,%1,%2,%3}, [%4];"
                 : "=r"(r[0]), "=r"(r[1]), "=r"(r[2]), "=r"(r[3]) : "r"(addr));
}
__device__ __forceinline__ void ldmx4t(uint32_t* r, uint32_t addr) {
    asm volatile("ldmatrix.sync.aligned.m8n8.x4.trans.shared.b16 {%0,%1,%2,%3}, [%4];"
                 : "=r"(r[0]), "=r"(r[1]), "=r"(r[2]), "=r"(r[3]) : "r"(addr));
}
__device__ __forceinline__ void mmaf16(float* d, const uint32_t* a,
                                       uint32_t b0, uint32_t b1) {
    asm volatile("mma.sync.aligned.m16n8k16.row.col.f32.f16.f16.f32 "
                 "{%0,%1,%2,%3}, {%4,%5,%6,%7}, {%8,%9}, {%0,%1,%2,%3};"
                 : "+f"(d[0]), "+f"(d[1]), "+f"(d[2]), "+f"(d[3])
                 : "r"(a[0]), "r"(a[1]), "r"(a[2]), "r"(a[3]), "r"(b0), "r"(b1));
}
__device__ __forceinline__ uint32_t packf16(float lo, float hi) {
    uint32_t r;
    asm("cvt.rn.f16x2.f32 %0, %1, %2;" : "=r"(r) : "f"(hi), "f"(lo));
    return r;
}
__device__ __forceinline__ float f16val(float x) {
    return __half2float(__float2half(x));
}
__device__ __forceinline__ uint32_t swzoff(int r, int chunk) {
    return (uint32_t)(r * 128 + ((chunk ^ (r & 7)) << 4));
}

// ---------------- RoPE cos/sin table -------------------------------------------
__global__ void rope_table_kernel() {
    int idx = blockIdx.x * blockDim.x + threadIdx.x;
    if (idx >= TT * (HD/2)) return;
    int t = idx / (HD/2);
    int i = idx % (HD/2);
    float inv = (float)pow(10000.0, -(double)(2*i) / (double)HD);
    float ang = (float)t * inv;
    g_cos[idx] = cosf(ang);
    g_sin[idx] = sinf(ang);
}

// ---------------- fp32 -> f16 (hi only), MLP=4 grid-stride -----------------------
__global__ void cvt_hi_kernel(const float* __restrict__ in,
                              __half* __restrict__ hi, int n4) {
    int tid = blockIdx.x * blockDim.x + threadIdx.x;
    int stride = gridDim.x * blockDim.x;
    float4 v[4];
    int idx[4];
#pragma unroll
    for (int k = 0; k < 4; k++) {
        idx[k] = tid + k * stride;
        if (idx[k] < n4) v[k] = ((const float4*)in)[idx[k]];
    }
#pragma unroll
    for (int k = 0; k < 4; k++) {
        if (idx[k] < n4) {
            uint2 o;
            o.x = packf16(v[k].x, v[k].y);
            o.y = packf16(v[k].z, v[k].w);
            ((uint2*)hi)[idx[k]] = o;
        }
    }
}

// ---------------- fp32 -> f16 hi, 4 weights, MLP=4 -------------------------------
__global__ void cvt_w4_kernel(const float* __restrict__ w0, const float* __restrict__ w1,
                              const float* __restrict__ w2, const float* __restrict__ w3,
                              __half* __restrict__ hi, int n4) {
    int tid = blockIdx.x * blockDim.x + threadIdx.x;
    int stride = gridDim.x * blockDim.x;
    int z = blockIdx.y;
    const float* in = (z == 0) ? w0 : (z == 1) ? w1 : (z == 2) ? w2 : w3;
    size_t base = (size_t)z * CC * CC / 4;
    float4 v[4];
    int idx[4];
#pragma unroll
    for (int k = 0; k < 4; k++) {
        idx[k] = tid + k * stride;
        if (idx[k] < n4) v[k] = ((const float4*)in)[idx[k]];
    }
#pragma unroll
    for (int k = 0; k < 4; k++) {
        if (idx[k] < n4) {
            uint2 h;
            h.x = packf16(v[k].x, v[k].y);
            h.y = packf16(v[k].z, v[k].w);
            ((uint2*)hi)[base + idx[k]] = h;
        }
    }
}

// ---------------- persistent f16 single-pass GEMM via TMA + mma.sync -------------
// CTA tile 256(M) x 128(N), BK=128 (2x 64-col SW128 subtiles), 2-stage flat
// cross-tile TMA pipeline, 512 threads / 16 warps (4m x 4n), warp tile 64x32.
// MODE 0: out-proj (fp32 out). MODE 1: qkv (f16-hi out, RoPE for z<2).
#define BM 256
#define BN 128
#define BK 128
#define NKIT (CC / BK)     // 16
#define B_OFF 65536        // A subtiles @0,32768; B subtiles @65536,81920
#define STG_SZ 98304
#define NSTG 2
#define GEMM_SMEM (2048 + NSTG*STG_SZ)
#define GTHREADS 512
#define GWARPS (GTHREADS/32)

template<int MODE>
__global__ __launch_bounds__(GTHREADS, 1)
void gemm_pers(const __grid_constant__ CUtensorMap tmA,
               const __grid_constant__ CUtensorMap tmB0,
               const __grid_constant__ CUtensorMap tmB1,
               const __grid_constant__ CUtensorMap tmB2,
               __half* __restrict__ qh,
               __half* __restrict__ kh,
               __half* __restrict__ vh,
               float* __restrict__ out) {
    extern __shared__ char smraw[];
    const uint32_t raw = smem_u32(smraw);
    const uint32_t ab = (raw + 64 + 1023) & ~1023u;
    const uint32_t fullb = raw;          // NSTG x 8B
    const uint32_t emptyb = raw + 16;    // NSTG x 8B
    const int tid = threadIdx.x;
    const int wid = tid >> 5, lane = tid & 31;
    const int wm = wid >> 2;             // 0..3  (64 rows each)
    const int wn = wid & 3;              // 0..3  (32 cols each)
    const int NT = (MODE == 1) ? (3 * (MM/BM) * (CC/BN)) : ((MM/BM) * (CC/BN));
    const int bx = blockIdx.x;
    const int grid = gridDim.x;
    if (bx >= NT) return;
    const int myTiles = (NT - bx + grid - 1) / grid;
    const int myChunks = myTiles * NKIT;

    if (tid == 0) {
#pragma unroll
        for (int s = 0; s < NSTG; s++) {
            MBAR_INIT(fullb + s * 8, 1);
            MBAR_INIT(emptyb + s * 8, GWARPS);   // warp-granular arrivals
        }
        asm volatile("fence.proxy.async.shared::cta;" ::: "memory");
    }
    __syncthreads();

    auto issue = [&](int g) {
        int lt = g >> 4;          // local tile (16 chunks/tile)
        int c = g & 15;
        int t = bx + lt * grid;
        int s = g & 1;
        uint32_t sb = ab + s * STG_SZ;
        uint32_t mb = fullb + s * 8;
        int z, mbk, nb;
        if (MODE == 1) { z = t >> 9; int r = t & 511; mbk = r >> 4; nb = r & 15; }
        else { z = 0; mbk = t >> 4; nb = t & 15; }
        const CUtensorMap* pb = (z == 0) ? &tmB0 : (z == 1) ? &tmB1 : &tmB2;
        MBAR_EXPECT(mb, (uint32_t)STG_SZ);
        int cx = c * BK;
        TMA2D(sb,             &tmA, cx,      mbk * BM, mb);
        TMA2D(sb + 32768,     &tmA, cx + 64, mbk * BM, mb);
        TMA2D(sb + B_OFF,     pb,   cx,      nb * BN, mb);
        TMA2D(sb + B_OFF + 16384, pb, cx + 64, nb * BN, mb);
    };

    if (tid == 0) {
        for (int g = 0; g < NSTG && g < myChunks; g++) issue(g);
    }

    float acc[4][4][4];
#pragma unroll
    for (int i = 0; i < 4; i++)
#pragma unroll
        for (int j = 0; j < 4; j++)
#pragma unroll
            for (int q = 0; q < 4; q++) acc[i][j][q] = 0.f;

    const int a_row = wm * 64 + (lane & 15);
    const int a_csel = lane >> 4;
    const int b_row = wn * 32 + ((lane >> 4) << 3) + (lane & 7);
    const int b_csel = (lane >> 3) & 1;
    const int tr = lane >> 2;
    const int tc = (lane & 3) << 1;

    for (int g = 0; g < myChunks; ++g) {
        int s = g & 1;
        int ph = (g >> 1) & 1;
        MBAR_WAIT(fullb + s * 8, ph);

        uint32_t sb = ab + s * STG_SZ;
#pragma unroll
        for (int ks = 0; ks < 8; ks++) {
            int hf = ks >> 2;               // K subtile (64 cols each)
            int lc = (ks & 3) << 1;
            uint32_t a4[4][4], b4[2][4];
            uint32_t abase = sb + hf * 32768;
            uint32_t bbase = sb + B_OFF + hf * 16384;
#pragma unroll
            for (int f = 0; f < 4; f++)
                ldmx4(a4[f], abase + swzoff(a_row + f * 16, lc + a_csel));
#pragma unroll
            for (int p = 0; p < 2; p++)
                ldmx4(b4[p], bbase + swzoff(b_row + p * 16, lc + b_csel));
#pragma unroll
            for (int mf = 0; mf < 4; mf++)
#pragma unroll
                for (int nf = 0; nf < 4; nf++) {
                    int p = nf >> 1;
                    int e = (nf & 1) << 1;
                    mmaf16(acc[mf][nf], a4[mf], b4[p][e], b4[p][e + 1]);
                }
        }
        if (lane == 0) MBAR_ARRIVE(emptyb + s * 8);   // one arrive per warp

        if (tid == 0 && g + NSTG < myChunks) {
            MBAR_WAIT(emptyb + s * 8, ph);
            issue(g + NSTG);
        }

        if ((g & 15) == 15) {
            // ---- epilogue for tile (g>>4); next tile's TMA already in flight ----
            int t = bx + (g >> 4) * grid;
            int z, mbk, nb;
            if (MODE == 1) { z = t >> 9; int r = t & 511; mbk = r >> 4; nb = r & 15; }
            else { z = 0; mbk = t >> 4; nb = t & 15; }
            int m0 = mbk * BM, n0 = nb * BN;
            __half* outH = (z == 0) ? qh : (z == 1) ? kh : vh;
            bool rope = (z < 2);
#pragma unroll
            for (int mf = 0; mf < 4; mf++) {
#pragma unroll
                for (int nf = 0; nf < 4; nf++) {
                    int mA = m0 + wm * 64 + mf * 16 + tr;
                    int n  = n0 + wn * 32 + nf * 8 + tc;
                    float* d = acc[mf][nf];
#pragma unroll
                    for (int hf = 0; hf < 2; hf++) {
                        int m = mA + hf * 8;
                        float e = d[hf * 2], o = d[hf * 2 + 1];
                        if (MODE == 0) {
                            float2 v2 = {e, o};
                            *(float2*)(out + (size_t)m * CC + n) = v2;
                        } else {
                            int b = m >> 11;
                            int tt = m & (TT - 1);
                            int h = n >> 7;
                            int dd = n & (HD - 1);
                            size_t dst = ((size_t)(b * NH + h) * TT + tt) * HD + dd;
                            float e2 = e, o2 = o;
                            if (rope) {
                                float cv = g_cos[tt * (HD/2) + (dd >> 1)];
                                float sv = g_sin[tt * (HD/2) + (dd >> 1)];
                                e2 = e * cv - o * sv;
                                o2 = o * cv + e * sv;
                            }
                            *(uint32_t*)((char*)outH + dst * 2) = packf16(e2, o2);
                        }
                        d[hf * 2] = 0.f; d[hf * 2 + 1] = 0.f;
                    }
                }
            }
        }
    }
}

// ---------------- tensor-core flash attention (f16 hi, causal) -------------------
// QK = Qh*Kh, PV = Ph*Vh. smem: Qh 16K | Kh 16K | Vh 16K. 3 CTAs/SM.
#define SQH 0
#define SKH 16384
#define SVH 32768
#define ATTN_SMEM (1024 + 49152)

__global__ __launch_bounds__(128, 3)
void attn_tc(const __grid_constant__ CUtensorMap mQh,
             const __grid_constant__ CUtensorMap mKh,
             const __grid_constant__ CUtensorMap mVh,
             __half* __restrict__ yh) {
    extern __shared__ char smraw[];
    const uint32_t raw = smem_u32(smraw);
    const uint32_t ab = (raw + 64 + 1023) & ~1023u;
    const uint32_t qfull = raw, kfull = raw + 8, vfull = raw + 16;
    const uint32_t kempty = raw + 24, vempty = raw + 32;
    const int tid = threadIdx.x, wid = tid >> 5, lane = tid & 31;
    const int qtile = gridDim.x - 1 - blockIdx.x;   // big tiles first
    const int bh = blockIdx.y;
    const int nt = qtile + 1;
    const int grow_q = bh * TT + qtile * 64;
    const int grow_k = bh * TT;

    if (tid == 0) {
        MBAR_INIT(qfull, 1); MBAR_INIT(kfull, 1); MBAR_INIT(vfull, 1);
        MBAR_INIT(kempty, 4); MBAR_INIT(vempty, 4);
        asm volatile("fence.proxy.async.shared::cta;" ::: "memory");
    }
    __syncthreads();
    if (tid == 0) {
        MBAR_EXPECT(qfull, 16384u);
        TMA2D(ab + SQH,        &mQh, 0,  grow_q, qfull);
        TMA2D(ab + SQH + 8192, &mQh, 64, grow_q, qfull);
        MBAR_EXPECT(kfull, 16384u);
        TMA2D(ab + SKH,        &mKh, 0,  grow_k, kfull);
        TMA2D(ab + SKH + 8192, &mKh, 64, grow_k, kfull);
        MBAR_EXPECT(vfull, 16384u);
        TMA2D(ab + SVH,        &mVh, 0,  grow_k, vfull);
        TMA2D(ab + SVH + 8192, &mVh, 64, grow_k, vfull);
    }

    float o[16][4];
#pragma unroll
    for (int i = 0; i < 16; i++)
#pragma unroll
        for (int q = 0; q < 4; q++) o[i][q] = 0.f;
    float m0r = -1e30f, m1r = -1e30f, l0r = 0.f, l1r = 0.f;

    const int q_row = wid * 16 + (lane & 15);
    const int q_csel = lane >> 4;
    const int k_rowbase = ((lane >> 4) << 3) + (lane & 7);
    const int k_csel = (lane >> 3) & 1;
    const int v_rowin = (lane & 7) + (((lane >> 3) & 1) << 3);
    const int v_csel = lane >> 4;
    const float scale = 0.08838834764831843f;

    MBAR_WAIT(qfull, 0);

    for (int j = 0; j < nt; j++) {
        MBAR_WAIT(kfull, j & 1);

        float s[8][4];
#pragma unroll
        for (int nf = 0; nf < 8; nf++)
#pragma unroll
            for (int q = 0; q < 4; q++) s[nf][q] = 0.f;

#pragma unroll
        for (int ks = 0; ks < 8; ks++) {
            int hf = ks >> 2;
            int lc = (ks & 3) << 1;
            uint32_t qh4[4];
            uint32_t qoff = hf * 8192 + swzoff(q_row, lc + q_csel);
            ldmx4(qh4, ab + SQH + qoff);
#pragma unroll
            for (int p = 0; p < 4; p++) {
                uint32_t kh4[4];
                uint32_t koff = hf * 8192 + swzoff(p * 16 + k_rowbase, lc + k_csel);
                ldmx4(kh4, ab + SKH + koff);
#pragma unroll
                for (int e2 = 0; e2 < 2; e2++) {
                    int nf = p * 2 + e2;
                    int e = e2 << 1;
                    mmaf16(s[nf], qh4, kh4[e], kh4[e + 1]);
                }
            }
        }
        if (lane == 0) MBAR_ARRIVE(kempty);
        if (tid == 0 && j + 1 < nt) {
            MBAR_WAIT(kempty, j & 1);
            MBAR_EXPECT(kfull, 16384u);
            int cy = grow_k + (j + 1) * 64;
            TMA2D(ab + SKH,        &mKh, 0,  cy, kfull);
            TMA2D(ab + SKH + 8192, &mKh, 64, cy, kfull);
        }

#pragma unroll
        for (int nf = 0; nf < 8; nf++)
#pragma unroll
            for (int q = 0; q < 4; q++) s[nf][q] *= scale;
        if (j == qtile) {
            int r0 = wid * 16 + (lane >> 2);
#pragma unroll
            for (int nf = 0; nf < 8; nf++) {
                int c0 = nf * 8 + ((lane & 3) << 1);
                if (c0     > r0)     s[nf][0] = -1e30f;
                if (c0 + 1 > r0)     s[nf][1] = -1e30f;
                if (c0     > r0 + 8) s[nf][2] = -1e30f;
                if (c0 + 1 > r0 + 8) s[nf][3] = -1e30f;
            }
        }

        float rm0 = -1e30f, rm1 = -1e30f;
#pragma unroll
        for (int nf = 0; nf < 8; nf++) {
            rm0 = fmaxf(rm0, fmaxf(s[nf][0], s[nf][1]));
            rm1 = fmaxf(rm1, fmaxf(s[nf][2], s[nf][3]));
        }
        rm0 = fmaxf(rm0, __shfl_xor_sync(0xffffffffu, rm0, 1));
        rm0 = fmaxf(rm0, __shfl_xor_sync(0xffffffffu, rm0, 2));
        rm1 = fmaxf(rm1, __shfl_xor_sync(0xffffffffu, rm1, 1));
        rm1 = fmaxf(rm1, __shfl_xor_sync(0xffffffffu, rm1, 2));
        float mn0 = fmaxf(m0r, rm0), mn1 = fmaxf(m1r, rm1);
        float al0 = __expf(m0r - mn0), al1 = __expf(m1r - mn1);
        m0r = mn0; m1r = mn1;

        float rs0 = 0.f, rs1 = 0.f;
        uint32_t aph[4][4];
#pragma unroll
        for (int ks2 = 0; ks2 < 4; ks2++) {
#pragma unroll
            for (int hn = 0; hn < 2; hn++) {
                int nf = 2 * ks2 + hn;
                float p0 = __expf(s[nf][0] - mn0);
                float p1 = __expf(s[nf][1] - mn0);
                float p2 = __expf(s[nf][2] - mn1);
                float p3 = __expf(s[nf][3] - mn1);
                rs0 += p0 + p1; rs1 += p2 + p3;
                aph[ks2][hn * 2]     = packf16(p0, p1);
                aph[ks2][hn * 2 + 1] = packf16(p2, p3);
            }
        }
        rs0 += __shfl_xor_sync(0xffffffffu, rs0, 1);
        rs0 += __shfl_xor_sync(0xffffffffu, rs0, 2);
        rs1 += __shfl_xor_sync(0xffffffffu, rs1, 1);
        rs1 += __shfl_xor_sync(0xffffffffu, rs1, 2);
        l0r = l0r * al0 + rs0;
        l1r = l1r * al1 + rs1;

#pragma unroll
        for (int ng = 0; ng < 16; ng++) {
            o[ng][0] *= al0; o[ng][1] *= al0;
            o[ng][2] *= al1; o[ng][3] *= al1;
        }

        MBAR_WAIT(vfull, j & 1);
#pragma unroll
        for (int ks2 = 0; ks2 < 4; ks2++) {
#pragma unroll
            for (int g = 0; g < 8; g++) {
                uint32_t vh4[4];
                int hf = g >> 2;
                uint32_t voff = hf * 8192 +
                                swzoff(ks2 * 16 + v_rowin, ((g & 3) << 1) + v_csel);
                ldmx4t(vh4, ab + SVH + voff);
#pragma unroll
                for (int e2 = 0; e2 < 2; e2++) {
                    int ng = g * 2 + e2;
                    int e = e2 << 1;
                    mmaf16(o[ng], aph[ks2], vh4[e], vh4[e + 1]);
                }
            }
        }
        if (lane == 0) MBAR_ARRIVE(vempty);
        if (tid == 0 && j + 1 < nt) {
            MBAR_WAIT(vempty, j & 1);
            MBAR_EXPECT(vfull, 16384u);
            int cy = grow_k + (j + 1) * 64;
            TMA2D(ab + SVH,        &mVh, 0,  cy, vfull);
            TMA2D(ab + SVH + 8192, &mVh, 64, cy, vfull);
        }
    }

    // epilogue: y (B,T,C) f16 hi
    float inv0 = 1.0f / l0r, inv1 = 1.0f / l1r;
    int b = bh >> 4, h = bh & 15;
    int t0 = qtile * 64 + wid * 16 + (lane >> 2);
    size_t base0 = (size_t)(b * TT + t0) * CC + h * HD;
    size_t base1 = base0 + (size_t)8 * CC;
    int c0 = (lane & 3) << 1;
#pragma unroll
    for (int ng = 0; ng < 16; ng++) {
        int col = ng * 8 + c0;
        *(uint32_t*)((char*)yh + (base0 + col) * 2) =
            packf16(o[ng][0] * inv0, o[ng][1] * inv0);
        *(uint32_t*)((char*)yh + (base1 + col) * 2) =
            packf16(o[ng][2] * inv1, o[ng][3] * inv1);
    }
}

// ---------------- host: tensormap encode via driver entry point ------------------
typedef CUresult (*EncodeFn)(CUtensorMap*, CUtensorMapDataType, cuuint32_t, void*,
                             const cuuint64_t*, const cuuint64_t*, const cuuint32_t*,
                             const cuuint32_t*, CUtensorMapInterleave, CUtensorMapSwizzle,
                             CUtensorMapL2promotion, CUtensorMapFloatOOBfill);

static void mk_map(EncodeFn enc, CUtensorMap* m, void* base, uint64_t cols,
                   uint64_t rows, uint32_t boxRows) {
    cuuint64_t dims[2] = {(cuuint64_t)cols, (cuuint64_t)rows};
    cuuint64_t strides[1] = {(cuuint64_t)cols * 2};
    cuuint32_t box[2] = {64u, boxRows};
    cuuint32_t es[2] = {1u, 1u};
    enc(m, CU_TENSOR_MAP_DATA_TYPE_FLOAT16, 2, base, dims, strides, box, es,
        CU_TENSOR_MAP_INTERLEAVE_NONE, CU_TENSOR_MAP_SWIZZLE_128B,
        CU_TENSOR_MAP_L2_PROMOTION_L2_128B, CU_TENSOR_MAP_FLOAT_OOB_FILL_NONE);
}

// ---------------- launch --------------------------------------------------------
extern "C" void kernel_launch(void* const* d_in, const int* in_sizes, int n_in,
                              void* d_out, int out_size) {
    const float* x  = (const float*)d_in[0];
    const float* Wq = (const float*)d_in[1];
    const float* Wk = (const float*)d_in[2];
    const float* Wv = (const float*)d_in[3];
    const float* Wp = (const float*)d_in[4];
    float* out = (float*)d_out;

    __half *xh, *yh, *wh;
    __half *qh, *kh, *vh;
    cudaGetSymbolAddress((void**)&xh, g_xh);
    cudaGetSymbolAddress((void**)&yh, g_yh);
    cudaGetSymbolAddress((void**)&wh, g_wh);
    cudaGetSymbolAddress((void**)&qh, g_qh);
    cudaGetSymbolAddress((void**)&kh, g_kh);
    cudaGetSymbolAddress((void**)&vh, g_vh);

    void* fn = nullptr;
    cudaDriverEntryPointQueryResult st;
    cudaGetDriverEntryPoint("cuTensorMapEncodeTiled", &fn, cudaEnableDefault, &st);
    EncodeFn enc = (EncodeFn)fn;
    const uint64_t QR = (uint64_t)BSZ * NH * TT;
    CUtensorMap mXh, mYh, mWh[4];
    CUtensorMap mQh, mKh, mVh;
    mk_map(enc, &mXh, xh, CC, MM, BM);
    mk_map(enc, &mYh, yh, CC, MM, BM);
    for (int i = 0; i < 4; i++)
        mk_map(enc, &mWh[i], wh + (size_t)i * CC * CC, CC, CC, BN);
    mk_map(enc, &mQh, qh, HD, QR, 64);
    mk_map(enc, &mKh, kh, HD, QR, 64);
    mk_map(enc, &mVh, vh, HD, QR, 64);

    int sms = 148;
    cudaDeviceGetAttribute(&sms, cudaDevAttrMultiProcessorCount, 0);

    rope_table_kernel<<<(TT * (HD/2) + 255) / 256, 256>>>();

    const int NX4 = MM * CC / 4;
    const int NW4 = CC * CC / 4;
    cvt_hi_kernel<<<(NX4/4 + 255) / 256, 256>>>(x, xh, NX4);
    cvt_w4_kernel<<<dim3((NW4/4 + 255) / 256, 4), 256>>>(Wq, Wk, Wv, Wp, wh, NW4);

    cudaFuncSetAttribute(gemm_pers<0>, cudaFuncAttributeMaxDynamicSharedMemorySize, GEMM_SMEM);
    cudaFuncSetAttribute(gemm_pers<1>, cudaFuncAttributeMaxDynamicSharedMemorySize, GEMM_SMEM);
    cudaFuncSetAttribute(attn_tc, cudaFuncAttributeMaxDynamicSharedMemorySize, ATTN_SMEM);

    gemm_pers<1><<<sms, GTHREADS, GEMM_SMEM>>>(mXh, mWh[0], mWh[1], mWh[2],
                                               qh, kh, vh, out);

    attn_tc<<<dim3(TT / 64, BSZ * NH), 128, ATTN_SMEM>>>(mQh, mKh, mVh, yh);

    gemm_pers<0><<<sms, GTHREADS, GEMM_SMEM>>>(mYh, mWh[3], mWh[3], mWh[3],
                                               qh, kh, vh, out);
}